// round 8
// baseline (speedup 1.0000x reference)
#include <cuda_runtime.h>

// Shapes fixed by setup_inputs():
//   grid:     (N=2, C=12, D=8, Hg=16, Wg=16) float32
//   guidemap: (N=2, 1, H=1024, W=1024)       float32
//   out:      (N=2, C=12, H=1024, W=1024)    float32
#define HW   (1024 * 1024)
#define Cc   12
#define HG   16
#define WG   16
#define Dd   8

// Per-row x/z table: entry s -> c = s/105, rem = s%105, x0 = rem/7, z0 = rem%7
//   tab4[s] = ( Gy(z0 ,x0), Gy(z0+1,x0), Gy(z0 ,x0+1), Gy(z0+1,x0+1) )
// where Gy = grid y-lerped at this row. 12*15*7 = 1260 float4, double-buffered.
#define NTAB 1260
#define MASTER_FLOATS (Cc * Dd * HG * WG)   // 24576
#define SMEM_BYTES (MASTER_FLOATS * 4 + 2 * NTAB * 16)   // 138,624 B

#define TPB 1024
#define BX  74     // 74 blocks * 2 batches = 148 = one block per SM

__global__ __launch_bounds__(TPB, 1)
void slice_operation_kernel(const float* __restrict__ grid,
                            const float* __restrict__ guide,
                            float* __restrict__ out)
{
    extern __shared__ float sm[];
    float*  master = sm;                                   // raw grid[n], 24576 f
    float4* tabs   = (float4*)(sm + MASTER_FLOATS);        // 2 x 1260 float4

    const int n   = blockIdx.y;
    const int tid = threadIdx.x;

    // ---- Stage master grid[n] (one time) ----
    const float* gsrc = grid + (size_t)n * MASTER_FLOATS;
    for (int s = tid; s < MASTER_FLOATS; s += TPB)
        master[s] = __ldg(gsrc + s);
    __syncthreads();

    const float* gmap  = guide + (size_t)n * HW;
    float*       obase = out   + (size_t)n * (size_t)Cc * HW;
    const float  sxy   = 15.0f / 1023.0f;

    // Table-entry decomposition (<= 2 entries per thread: tid and tid+1024)
    const int s0 = tid;
    const int c0 = s0 / 105; { }
    const int r0 = s0 - c0 * 105;
    const int x0a = r0 / 7, z0a = r0 - x0a * 7;
    const int s1 = tid + TPB;
    const bool has1 = (s1 < NTAB);
    int c1 = 0, x0b = 0, z0b = 0;
    if (has1) { c1 = s1 / 105; int r1 = s1 - c1 * 105; x0b = r1 / 7; z0b = r1 - x0b * 7; }

    // Per-thread x interpolation is row-invariant (x == tid)
    const float fx  = (float)tid * sxy;
    const int   ix0 = min((int)fx, WG - 2);
    const float wx  = fx - (float)ix0;
    const float wx0 = 1.0f - wx;

    int   y    = blockIdx.x;
    float gcur = gmap[(size_t)y * 1024 + tid];   // guide prefetch (row y)
    int   buf  = 0;

    while (y < 1024) {
        // ---- Build tab[buf] for row y (y-lerp of grid) ----
        const float fy  = (float)y * sxy;
        const int   iy0 = min((int)fy, HG - 2);
        const float wy  = fy - (float)iy0;
        {
            const float* b = master + ((c0 * Dd + z0a) * HG + iy0) * WG + x0a;
            float4 e;
            e.x = b[0]   + wy * (b[WG]       - b[0]);      // z0  , x0
            e.y = b[256] + wy * (b[256 + WG] - b[256]);    // z0+1, x0
            e.z = b[1]   + wy * (b[1 + WG]   - b[1]);      // z0  , x0+1
            e.w = b[257] + wy * (b[257 + WG] - b[257]);    // z0+1, x0+1
            tabs[buf * NTAB + s0] = e;
            if (has1) {
                const float* b2 = master + ((c1 * Dd + z0b) * HG + iy0) * WG + x0b;
                float4 e2;
                e2.x = b2[0]   + wy * (b2[WG]       - b2[0]);
                e2.y = b2[256] + wy * (b2[256 + WG] - b2[256]);
                e2.z = b2[1]   + wy * (b2[1 + WG]   - b2[1]);
                e2.w = b2[257] + wy * (b2[257 + WG] - b2[257]);
                tabs[buf * NTAB + s1] = e2;
            }
        }
        __syncthreads();   // one barrier per row (double-buffered tables)

        const int ynext = y + BX;
        float gnext = 0.0f;
        if (ynext < 1024) gnext = gmap[(size_t)ynext * 1024 + tid];  // prefetch

        // ---- Process row y: pixel x = tid, bilinear in (x, z) ----
        const float fz = fminf(fmaxf(gcur * (float)(Dd - 1), 0.0f), (float)(Dd - 1));
        const int   z0 = min((int)fz, Dd - 2);
        const float wz = fz - (float)z0;
        const float wz0 = 1.0f - wz;
        const float w00 = wx0 * wz0, w01 = wx0 * wz;
        const float w10 = wx  * wz0, w11 = wx  * wz;

        const float4* t  = tabs + buf * NTAB + ix0 * 7 + z0;
        float*        op = obase + (size_t)y * 1024 + tid;
        #pragma unroll
        for (int c = 0; c < Cc; c++) {
            float4 q = t[c * 105];
            op[(size_t)c * HW] = q.x * w00 + q.y * w01 + q.z * w10 + q.w * w11;
        }

        gcur = gnext;
        y    = ynext;
        buf ^= 1;
    }
}

extern "C" void kernel_launch(void* const* d_in, const int* in_sizes, int n_in,
                              void* d_out, int out_size)
{
    const float* grid  = (const float*)d_in[0];
    const float* guide = (const float*)d_in[1];
    float*       out   = (float*)d_out;

    cudaFuncSetAttribute(slice_operation_kernel,
                         cudaFuncAttributeMaxDynamicSharedMemorySize, SMEM_BYTES);

    dim3 gdim(BX, 2);
    slice_operation_kernel<<<gdim, TPB, SMEM_BYTES>>>(grid, guide, out);
}

// round 9
// speedup vs baseline: 1.1494x; 1.1494x over previous
#include <cuda_runtime.h>
#include <cstdint>

// Shapes fixed by setup_inputs():
//   grid:     (N=2, C=12, D=8, Hg=16, Wg=16) float32
//   guidemap: (N=2, 1, H=1024, W=1024)       float32
//   out:      (N=2, C=12, H=1024, W=1024)    float32
#define HW   (1024 * 1024)
#define Cc   12
#define Dd   8
#define HG   16
#define WG   16

// SMEM: fp32 z-pair table, float2 element e = ((c*16 + y)*16 + x)*7 + z0
//   value = ( g[c,z0,y,x], g[c,z0+1,y,x] )
// Per-warp gathers dedup to <=14 consecutive e values -> distinct banks,
// conflict-free, ~1 crossbar phase per LDS.64.
#define PT7  7
#define XS   7                   // x   stride (float2 units)
#define YS   (WG * PT7)          // 112 y stride
#define CS   (HG * WG * PT7)     // 1792 float2 per channel
#define NEL  (Cc * CS)           // 21504 float2
#define SMEM_BYTES (NEL * 8)     // 172,032 B (fits 227 KB, occ = 1 block/SM)

#define TPB    1024
#define NBLK_X 74                // 74 * 2 batches = 148 = one full wave

// Packed fp32x2 FMA (sm_10x; FFMA2 in SASS — PTX-only, ptxas won't auto-fuse)
__device__ __forceinline__ uint64_t fma_f32x2(uint64_t a, uint64_t b, uint64_t c) {
    uint64_t d;
    asm("fma.rn.f32x2 %0, %1, %2, %3;" : "=l"(d) : "l"(a), "l"(b), "l"(c));
    return d;
}
__device__ __forceinline__ uint64_t mul_f32x2(uint64_t a, uint64_t b) {
    uint64_t d;
    asm("mul.rn.f32x2 %0, %1, %2;" : "=l"(d) : "l"(a), "l"(b));
    return d;
}
__device__ __forceinline__ uint64_t pack2(float lo, float hi) {
    uint64_t d;
    asm("mov.b64 %0, {%1, %2};" : "=l"(d) : "f"(lo), "f"(hi));
    return d;
}
__device__ __forceinline__ float sum2(uint64_t v) {
    float lo, hi;
    asm("mov.b64 {%0, %1}, %2;" : "=f"(lo), "=f"(hi) : "l"(v));
    return lo + hi;
}

__global__ __launch_bounds__(TPB, 1)
void slice_operation_kernel(const float* __restrict__ grid,
                            const float* __restrict__ guide,
                            float* __restrict__ out)
{
    extern __shared__ float2 sg[];
    const int n = blockIdx.y;

    // ---- Stage grid[n] as fp32 z-pairs ----
    const float* gsrc = grid + (size_t)n * (Cc * Dd * HG * WG);
    for (int s = threadIdx.x; s < NEL; s += TPB) {
        int c  = s / CS;
        int r  = s - c * CS;
        int pt = r / PT7;            // y*16 + x
        int z0 = r - pt * PT7;
        float g0 = __ldg(gsrc + (c * Dd + z0)     * 256 + pt);
        float g1 = __ldg(gsrc + (c * Dd + z0 + 1) * 256 + pt);
        sg[s] = make_float2(g0, g1);
    }
    __syncthreads();

    const unsigned long long* tq = (const unsigned long long*)sg;
    const float* gmap  = guide + (size_t)n * HW;
    float*       obase = out   + (size_t)n * (size_t)Cc * HW;

    const float sxy = 15.0f / 1023.0f;   // (Hg-1)/(H-1) == (Wg-1)/(W-1)

    for (int p = blockIdx.x * TPB + threadIdx.x; p < HW; p += NBLK_X * TPB) {
        const int y = p >> 10;
        const int x = p & 1023;

        float fy = (float)y * sxy;
        float fx = (float)x * sxy;
        int iy0 = min((int)fy, HG - 2);     // clamp floor; weight saturates at edge
        int ix0 = min((int)fx, WG - 2);
        float wy = fy - (float)iy0;
        float wx = fx - (float)ix0;

        float g  = __ldg(gmap + p);
        float fz = fminf(fmaxf(g * (float)(Dd - 1), 0.0f), (float)(Dd - 1));
        int iz0 = min((int)fz, Dd - 2);
        float wz = fz - (float)iz0;

        // 4 packed corner weight vectors: (w_yx * (1-wz), w_yx * wz)
        float wy0 = 1.0f - wy, wx0 = 1.0f - wx, wz0 = 1.0f - wz;
        float w00 = wy0 * wx0, w01 = wy0 * wx, w10 = wy * wx0, w11 = wy * wx;
        uint64_t wv00 = pack2(w00 * wz0, w00 * wz);
        uint64_t wv01 = pack2(w01 * wz0, w01 * wz);
        uint64_t wv10 = pack2(w10 * wz0, w10 * wz);
        uint64_t wv11 = pack2(w11 * wz0, w11 * wz);

        const int base = (iy0 * WG + ix0) * PT7 + iz0;
        float* op = obase + p;

        #pragma unroll
        for (int c = 0; c < Cc; c++) {
            const unsigned long long* t = tq + c * CS + base;
            uint64_t acc = mul_f32x2(t[0],       wv00);     // (y0,x0)
            acc = fma_f32x2(t[XS],      wv01, acc);         // (y0,x1)
            acc = fma_f32x2(t[YS],      wv10, acc);         // (y1,x0)
            acc = fma_f32x2(t[YS + XS], wv11, acc);         // (y1,x1)
            op[(size_t)c * HW] = sum2(acc);                 // z0 + z1 lanes
        }
    }
}

extern "C" void kernel_launch(void* const* d_in, const int* in_sizes, int n_in,
                              void* d_out, int out_size)
{
    const float* grid  = (const float*)d_in[0];
    const float* guide = (const float*)d_in[1];
    float*       out   = (float*)d_out;

    cudaFuncSetAttribute(slice_operation_kernel,
                         cudaFuncAttributeMaxDynamicSharedMemorySize, SMEM_BYTES);

    dim3 gdim(NBLK_X, 2);
    slice_operation_kernel<<<gdim, TPB, SMEM_BYTES>>>(grid, guide, out);
}

// round 10
// speedup vs baseline: 1.4777x; 1.2856x over previous
#include <cuda_runtime.h>
#include <cstdint>

// Shapes fixed by setup_inputs():
//   grid:     (N=2, C=12, D=8, Hg=16, Wg=16) float32
//   guidemap: (N=2, 1, H=1024, W=1024)       float32
//   out:      (N=2, C=12, H=1024, W=1024)    float32
#define HW   (1024 * 1024)
#define Cc   12
#define Dd   8
#define HG   16
#define WG   16

#define MASTER_F (Cc * Dd * HG * WG)        // 24576 floats (raw grid[n])
// Per-row y-lerped table: float2 idx = (c*16 + x)*7 + z0,
//   value = ( Gy[c,z0,x], Gy[c,z0+1,x] ), Gy = grid lerped at this row's y.
// Pixel gathers: per warp <=14 consecutive float2 slots -> conflict-free.
#define NTAB (Cc * 16 * 7)                  // 1344 float2
#define SMEM_BYTES (MASTER_F * 4 + 2 * NTAB * 8)   // 98304 + 21504 = 119808 B

#define TPB 1024   // == image width: one row per block-iteration
#define BX  74     // 74 blocks * 2 batches = 148 = one block per SM

// Packed fp32x2 ops (FFMA2 in SASS — PTX-only)
static __device__ __forceinline__ uint64_t fma_f32x2(uint64_t a, uint64_t b, uint64_t c) {
    uint64_t d; asm("fma.rn.f32x2 %0, %1, %2, %3;" : "=l"(d) : "l"(a), "l"(b), "l"(c)); return d;
}
static __device__ __forceinline__ uint64_t mul_f32x2(uint64_t a, uint64_t b) {
    uint64_t d; asm("mul.rn.f32x2 %0, %1, %2;" : "=l"(d) : "l"(a), "l"(b)); return d;
}
static __device__ __forceinline__ uint64_t pack2(float lo, float hi) {
    uint64_t d; asm("mov.b64 %0, {%1, %2};" : "=l"(d) : "f"(lo), "f"(hi)); return d;
}
static __device__ __forceinline__ float sum2(uint64_t v) {
    float lo, hi; asm("mov.b64 {%0, %1}, %2;" : "=f"(lo), "=f"(hi) : "l"(v)); return lo + hi;
}

__global__ __launch_bounds__(TPB, 1)
void slice_operation_kernel(const float* __restrict__ grid,
                            const float* __restrict__ guide,
                            float* __restrict__ out)
{
    extern __shared__ float sm[];
    float2* tabs = (float2*)(sm + MASTER_F);     // 2 x 1344 float2 (double buffer)
    const int n   = blockIdx.y;
    const int tid = threadIdx.x;

    // ---- Stage raw grid[n] once ----
    const float* gsrc = grid + (size_t)n * MASTER_F;
    for (int s = tid; s < MASTER_F; s += TPB) sm[s] = __ldg(gsrc + s);
    __syncthreads();

    // ---- Build-entry decode (x-fastest enumeration -> conflict-free master reads).
    // s = (c*7 + z0)*16 + x ; write index = (c*16 + x)*7 + z0 (z-fastest table).
    const int xa = tid & 15, ua = tid >> 4;          // ua in 0..63
    const int za = ua % 7,  ca = ua / 7;
    const int s1 = tid + TPB;                        // second entry for tid < 320
    const bool has1 = (s1 < NTAB);
    const int xb = s1 & 15, ub = s1 >> 4;
    const int zb = ub % 7,  cb = ub / 7;
    const int wia = (ca * 16 + xa) * 7 + za;
    const int wib = (cb * 16 + xb) * 7 + zb;

    const float sxy = 15.0f / 1023.0f;
    // Per-thread x interpolation is row-invariant (pixel column == tid)
    const float fx  = (float)tid * sxy;
    const int   ix0 = min((int)fx, WG - 2);
    const float wx  = fx - (float)ix0;
    const float wxc = 1.0f - wx;

    const float* gmap  = guide + (size_t)n * HW;
    float*       obase = out   + (size_t)n * (size_t)Cc * HW;

    int   y    = blockIdx.x;
    float gcur = gmap[(size_t)y * 1024 + tid];       // guide prefetch (row y)
    int   buf  = 0;

    while (y < 1024) {
        const float fy  = (float)y * sxy;
        const int   iy0 = min((int)fy, HG - 2);
        const float wy  = fy - (float)iy0;

        // ---- Build this row's y-lerped z-pair table ----
        {
            const float* m = sm + ((ca * Dd + za) * HG + iy0) * WG + xa;
            float lo = m[0]   + wy * (m[WG]       - m[0]);     // z0
            float hi = m[256] + wy * (m[256 + WG] - m[256]);   // z0+1
            tabs[buf * NTAB + wia] = make_float2(lo, hi);
            if (has1) {
                const float* m2 = sm + ((cb * Dd + zb) * HG + iy0) * WG + xb;
                float lo2 = m2[0]   + wy * (m2[WG]       - m2[0]);
                float hi2 = m2[256] + wy * (m2[256 + WG] - m2[256]);
                tabs[buf * NTAB + wib] = make_float2(lo2, hi2);
            }
        }
        __syncthreads();     // one barrier per row (double-buffered)

        const int ynext = y + BX;
        float gnext = 0.0f;
        if (ynext < 1024) gnext = gmap[(size_t)ynext * 1024 + tid];   // prefetch

        // ---- Pixel (row y, column tid): bilinear in (x, z) via FFMA2 ----
        const float fz  = fminf(fmaxf(gcur * (float)(Dd - 1), 0.0f), (float)(Dd - 1));
        const int   iz0 = min((int)fz, Dd - 2);
        const float wz  = fz - (float)iz0;
        const float wzc = 1.0f - wz;
        const uint64_t wv0 = pack2(wxc * wzc, wxc * wz);   // x0 weights (z0, z1)
        const uint64_t wv1 = pack2(wx  * wzc, wx  * wz);   // x1 weights (z0, z1)

        const unsigned long long* t =
            (const unsigned long long*)(tabs + buf * NTAB) + ix0 * 7 + iz0;
        float* op = obase + (size_t)y * 1024 + tid;

        #pragma unroll
        for (int c = 0; c < Cc; c++) {
            const unsigned long long* tc = t + c * 112;    // 16*7 per channel
            uint64_t acc = mul_f32x2(tc[0], wv0);          // x0 z-pair
            acc = fma_f32x2(tc[7], wv1, acc);              // x0+1 z-pair
            op[(size_t)c * HW] = sum2(acc);                // z0 + z1 lanes
        }

        gcur = gnext;
        y    = ynext;
        buf ^= 1;
    }
}

extern "C" void kernel_launch(void* const* d_in, const int* in_sizes, int n_in,
                              void* d_out, int out_size)
{
    const float* grid  = (const float*)d_in[0];
    const float* guide = (const float*)d_in[1];
    float*       out   = (float*)d_out;

    cudaFuncSetAttribute(slice_operation_kernel,
                         cudaFuncAttributeMaxDynamicSharedMemorySize, SMEM_BYTES);

    dim3 gdim(BX, 2);
    slice_operation_kernel<<<gdim, TPB, SMEM_BYTES>>>(grid, guide, out);
}